// round 17
// baseline (speedup 1.0000x reference)
#include <cuda_runtime.h>
#include <cuda_fp16.h>
#include <stdint.h>

#define D_MODEL 1024
#define NHEAD   16
#define DK      64
#define BATCH   2
#define SEQ     2048
#define MTOT    (BATCH*SEQ)   // 4096
#define NELEM   ((size_t)MTOT*D_MODEL)
#define NW      ((size_t)D_MODEL*D_MODEL)

// ---------------- scratch (static device globals; no allocations) ----------
__device__ __half g_qh[NELEM], g_kh[NELEM], g_vh[NELEM];
__device__ __half g_wqh[NW], g_wkh[NW], g_wvh[NW], g_woh[NW];
__device__ __half g_pq [NELEM];            // Q hi (pre-scaled 0.125*log2e)
__device__ __half g_pkv[3][NELEM];         // Kh, Kl, Vh
__device__ __half g_po [NELEM];            // attn out hi [b][s][h*64+d]

// ======================= low-level helpers (base ISA only) ================
__device__ __forceinline__ unsigned smem_u32(const void* p) {
    unsigned a;
    asm("{ .reg .u64 t; cvta.to.shared.u64 t, %1; cvt.u32.u64 %0, t; }" : "=r"(a) : "l"(p));
    return a;
}
__device__ __forceinline__ void cp16(unsigned dst, const void* src) {
    asm volatile("cp.async.cg.shared.global [%0], [%1], 16;" :: "r"(dst), "l"(src));
}
#define CP_COMMIT() asm volatile("cp.async.commit_group;" ::: "memory")
#define CP_WAIT1()  asm volatile("cp.async.wait_group 1;"  ::: "memory")
#define CP_WAIT0()  asm volatile("cp.async.wait_group 0;"  ::: "memory")

#define LDSM4(r, a) \
    asm volatile("ldmatrix.sync.aligned.m8n8.x4.shared.b16 {%0,%1,%2,%3}, [%4];" \
        : "=r"((r)[0]), "=r"((r)[1]), "=r"((r)[2]), "=r"((r)[3]) : "r"(a))
#define LDSM4T(r, a) \
    asm volatile("ldmatrix.sync.aligned.m8n8.x4.trans.shared.b16 {%0,%1,%2,%3}, [%4];" \
        : "=r"((r)[0]), "=r"((r)[1]), "=r"((r)[2]), "=r"((r)[3]) : "r"(a))

#define MMA4F(d, a, b0, b1) \
    asm volatile("mma.sync.aligned.m16n8k16.row.col.f32.f16.f16.f32 " \
        "{%0,%1,%2,%3}, {%4,%5,%6,%7}, {%8,%9}, {%0,%1,%2,%3};" \
        : "+f"((d)[0]), "+f"((d)[1]), "+f"((d)[2]), "+f"((d)[3]) \
        : "r"((a)[0]), "r"((a)[1]), "r"((a)[2]), "r"((a)[3]), "r"(b0), "r"(b1))

__device__ __forceinline__ float fexp2(float x) {
    float y; asm("ex2.approx.f32 %0, %1;" : "=f"(y) : "f"(x)); return y;
}
__device__ __forceinline__ unsigned pack_h2(float x, float y) {
    __half2 h = __float22half2_rn(make_float2(x, y));
    return *(unsigned*)&h;
}
__device__ __forceinline__ void split2h(float x, float y, unsigned& hi, unsigned& lo) {
    __half2 h = __float22half2_rn(make_float2(x, y));
    float2 hf = __half22float2(h);
    __half2 l = __float22half2_rn(make_float2(x - hf.x, y - hf.y));
    hi = *(unsigned*)&h; lo = *(unsigned*)&l;
}

// ======================= convert kernel: fp32 -> fp16 =======================
__global__ __launch_bounds__(256) void split_all(
    const float* q, const float* k, const float* v,
    const float* wq, const float* wk, const float* wv, const float* wo)
{
    const int z = blockIdx.y;
    const float* src; __half* dh; int n4;
    const int NA4 = MTOT*D_MODEL/4, NW4 = D_MODEL*D_MODEL/4;
    switch (z) {
        case 0: src = q;  dh = g_qh;  n4 = NA4; break;
        case 1: src = k;  dh = g_kh;  n4 = NA4; break;
        case 2: src = v;  dh = g_vh;  n4 = NA4; break;
        case 3: src = wq; dh = g_wqh; n4 = NW4; break;
        case 4: src = wk; dh = g_wkh; n4 = NW4; break;
        case 5: src = wv; dh = g_wvh; n4 = NW4; break;
        default:src = wo; dh = g_woh; n4 = NW4; break;
    }
    for (int i = blockIdx.x * blockDim.x + threadIdx.x; i < n4; i += gridDim.x * blockDim.x) {
        float4 vv = ((const float4*)src)[i];
        uint2 o;
        o.x = pack_h2(vv.x, vv.y);
        o.y = pack_h2(vv.z, vv.w);
        ((uint2*)dh)[i] = o;
    }
}

// ======================= HMMA GEMM core (plain fp16, f32 accum) ============
// C = Ah*Bh. BM=BN=128, BK=32, 128 thr (4 warps = 2x2), warp tile 64x64,
// 3 stages. Stage 16KB: Ah@0, Bh@8K. A-frags reused over 4 m-tiles.
#define G_STAGE 16384
#define G_SMEM  (3*G_STAGE)

__device__ __forceinline__ void gemm_load_stage(
    unsigned st, const __half* Ah, const __half* Bh,
    int m0, int n0, int k0, int tid)
{
    const __half* srcs[2] = {Ah, Bh};
    #pragma unroll
    for (int tt = 0; tt < 2; ++tt) {
        const int r0 = (tt == 0) ? m0 : n0;
        const __half* s = srcs[tt];
        #pragma unroll
        for (int i = 0; i < 4; ++i) {
            int idx = tid + i * 128;
            int row = idx >> 2, kc = idx & 3;
            unsigned d = st + tt * 8192 + row * 64 + (((kc ^ ((row >> 1) & 3))) << 4);
            cp16(d, s + (size_t)(r0 + row) * D_MODEL + k0 + kc * 8);
        }
    }
}

__device__ __forceinline__ void gemm_compute(
    const __half* Ah, const __half* Bh,
    int m0, int n0, unsigned sb, int tid, float acc[4][8][4])
{
    const int lane = tid & 31, wid = tid >> 5;
    const int wm = wid & 1, wn = wid >> 1;

    gemm_load_stage(sb,            Ah, Bh, m0, n0, 0,  tid); CP_COMMIT();
    gemm_load_stage(sb + G_STAGE,  Ah, Bh, m0, n0, 32, tid); CP_COMMIT();

    for (int it = 0; it < 32; ++it) {
        CP_WAIT1();
        __syncthreads();
        if (it + 2 < 32)
            gemm_load_stage(sb + ((it + 2) % 3) * G_STAGE, Ah, Bh,
                            m0, n0, (it + 2) * 32, tid);
        CP_COMMIT();
        const unsigned st = sb + (it % 3) * G_STAGE;
        #pragma unroll
        for (int ks = 0; ks < 2; ++ks) {
            unsigned aH[4][4];
            #pragma unroll
            for (int mt = 0; mt < 4; ++mt) {
                int row = wm * 64 + mt * 16 + (lane & 15);
                int kc  = 2 * ks + (lane >> 4);
                unsigned off = row * 64 + (((kc ^ ((row >> 1) & 3))) << 4);
                LDSM4(aH[mt], st + off);
            }
            #pragma unroll
            for (int q = 0; q < 4; ++q) {
                unsigned bH[4];
                int row = wn * 64 + q * 16 + (lane & 7) + 8 * ((lane >> 4) & 1);
                int kc  = 2 * ks + ((lane >> 3) & 1);
                unsigned off = row * 64 + (((kc ^ ((row >> 1) & 3))) << 4);
                LDSM4(bH, st + 8192 + off);
                #pragma unroll
                for (int mt = 0; mt < 4; ++mt) {
                    MMA4F(acc[mt][2*q],   aH[mt], bH[0], bH[1]);
                    MMA4F(acc[mt][2*q+1], aH[mt], bH[2], bH[3]);
                }
            }
        }
    }
}

// ---------------- QKV projection: grid (8, 32, 3), 128 thr -----------------
__global__ void __launch_bounds__(128, 2) tc_qkv(
    const float* __restrict__ bq, const float* __restrict__ bk,
    const float* __restrict__ bv)
{
    extern __shared__ char smem[];
    const unsigned sb = smem_u32(smem);
    const int z = blockIdx.z;
    const __half *Ah, *Bh;
    __half *dh, *dl;
    const float* bias;
    float scale;
    if (z == 0)      { Ah=g_qh; Bh=g_wqh; dh=g_pq;     dl=0;        bias=bq; scale=0.18033688f; }
    else if (z == 1) { Ah=g_kh; Bh=g_wkh; dh=g_pkv[0]; dl=g_pkv[1]; bias=bk; scale=1.0f; }
    else             { Ah=g_vh; Bh=g_wvh; dh=g_pkv[2]; dl=0;        bias=bv; scale=1.0f; }

    const int n0 = blockIdx.x * 128, m0 = blockIdx.y * 128;
    const int tid = threadIdx.x, lane = tid & 31, wid = tid >> 5;
    const int wm = wid & 1, wn = wid >> 1;

    float acc[4][8][4] = {};
    gemm_compute(Ah, Bh, m0, n0, sb, tid, acc);

    #pragma unroll
    for (int nt = 0; nt < 8; ++nt) {
        int n = n0 + wn * 64 + nt * 8 + (lane & 3) * 2;
        float b0v = bias[n], b1v = bias[n + 1];
        int hd = n >> 6, d = n & 63;
        #pragma unroll
        for (int mt = 0; mt < 4; ++mt) {
            #pragma unroll
            for (int half = 0; half < 2; ++half) {
                int m = m0 + wm * 64 + mt * 16 + (lane >> 2) + 8 * half;
                float x = (acc[mt][nt][2*half+0] + b0v) * scale;
                float y = (acc[mt][nt][2*half+1] + b1v) * scale;
                size_t dst = ((size_t)((m >> 11) * NHEAD + hd) * SEQ + (m & (SEQ-1))) * DK + d;
                if (dl) {
                    unsigned hi, lo; split2h(x, y, hi, lo);
                    *(unsigned*)(dh + dst) = hi;
                    *(unsigned*)(dl + dst) = lo;
                } else {
                    *(unsigned*)(dh + dst) = pack_h2(x, y);
                }
            }
        }
    }
}

// ---------------- output projection: grid (8, 32), 128 thr -----------------
__global__ void __launch_bounds__(128, 2) tc_out(
    const float* __restrict__ bias, float* __restrict__ out)
{
    extern __shared__ char smem[];
    const unsigned sb = smem_u32(smem);
    const int n0 = blockIdx.x * 128, m0 = blockIdx.y * 128;
    const int tid = threadIdx.x, lane = tid & 31, wid = tid >> 5;
    const int wm = wid & 1, wn = wid >> 1;

    float acc[4][8][4] = {};
    gemm_compute(g_po, g_woh, m0, n0, sb, tid, acc);

    #pragma unroll
    for (int nt = 0; nt < 8; ++nt) {
        int n = n0 + wn * 64 + nt * 8 + (lane & 3) * 2;
        float b0v = bias[n], b1v = bias[n + 1];
        #pragma unroll
        for (int mt = 0; mt < 4; ++mt) {
            #pragma unroll
            for (int half = 0; half < 2; ++half) {
                int m = m0 + wm * 64 + mt * 16 + (lane >> 2) + 8 * half;
                float2 vv = make_float2(acc[mt][nt][2*half+0] + b0v,
                                        acc[mt][nt][2*half+1] + b1v);
                *(float2*)(out + (size_t)m * D_MODEL + n) = vv;
            }
        }
    }
}

// ---------------- flash attention on HMMA: grid (16, 16, 2), 128 thr -------
// Br=128 (warp w owns rows 32w..32w+31, 2 m-tiles), Bc=32, 64 KV tiles.
// S = Qh*Kh + Qh*Kl ; O += Ph*Vh. K/V fragments amortized over 2 m-tiles.
// Q fragments in registers. SMEM: 3 stages x 12KB (Kh@0,Kl@4K,Vh@8K) = 36KB.
#define A_STAGE 12288
#define A_SMEM  (3*A_STAGE)

__device__ __forceinline__ void attn_load_stage(
    unsigned st, const __half* kvbase, int tid)
{
    #pragma unroll
    for (int tt = 0; tt < 3; ++tt) {
        const __half* s = kvbase + (size_t)tt * NELEM;
        #pragma unroll
        for (int i = 0; i < 2; ++i) {
            int idx = tid + i * 128;         // 0..255 chunks (32 rows x 8)
            int row = idx >> 3, dc = idx & 7;
            unsigned d = st + tt * 4096 + row * 128 + (((dc ^ (row & 7))) << 4);
            cp16(d, s + (size_t)row * DK + dc * 8);
        }
    }
}

__global__ void __launch_bounds__(128, 3) attn_mma() {
    extern __shared__ char smem[];
    const unsigned sb = smem_u32(smem);
    const int tid = threadIdx.x, lane = tid & 31, w = tid >> 5;
    const int qt = blockIdx.x, h = blockIdx.y, b = blockIdx.z;

    const size_t headoff = ((size_t)(b * NHEAD + h)) * SEQ * DK;
    const __half* qbase  = g_pq + headoff + (size_t)qt * 128 * DK;
    const __half* kvbase = &g_pkv[0][0] + headoff;

    // ---- prologue: stage Q (128 rows, spans stages 0..1), park frags ------
    #pragma unroll
    for (int i = 0; i < 8; ++i) {
        int idx = tid + i * 128;             // 0..1023 (128 rows x 8)
        int row = idx >> 3, dc = idx & 7;
        cp16(sb + row * 128 + (((dc ^ (row & 7))) << 4),
             qbase + (size_t)row * DK + dc * 8);
    }
    CP_COMMIT(); CP_WAIT0();
    __syncthreads();

    unsigned qh_f[2][4][4];
    #pragma unroll
    for (int mt = 0; mt < 2; ++mt)
        #pragma unroll
        for (int ks = 0; ks < 4; ++ks) {
            int row = 32 * w + mt * 16 + (lane & 15);
            int dc  = 2 * ks + (lane >> 4);
            unsigned off = row * 128 + (((dc ^ (row & 7))) << 4);
            LDSM4(qh_f[mt][ks], sb + off);
        }
    __syncthreads();   // Q staging area free before KV pipeline reuses it

    attn_load_stage(sb,           kvbase, tid);            CP_COMMIT();
    attn_load_stage(sb + A_STAGE, kvbase + 32 * DK, tid);  CP_COMMIT();

    float s_m[2][2] = {{-1e30f, -1e30f}, {-1e30f, -1e30f}};
    float s_l[2][2] = {{0.f, 0.f}, {0.f, 0.f}};
    float o[2][8][4] = {};

    for (int t = 0; t < 64; ++t) {
        CP_WAIT1();
        __syncthreads();
        if (t + 2 < 64)
            attn_load_stage(sb + ((t + 2) % 3) * A_STAGE,
                            kvbase + (size_t)(t + 2) * 32 * DK, tid);
        CP_COMMIT();
        const unsigned st = sb + (t % 3) * A_STAGE;

        // ---- S = Qh Kh^T + Qh Kl^T (K frags shared across m-tiles) ----
        float s[2][4][4] = {};
        #pragma unroll
        for (int ks = 0; ks < 4; ++ks) {
            unsigned bh[2][4], bl[2][4];
            #pragma unroll
            for (int q4 = 0; q4 < 2; ++q4) {
                int krow = q4 * 16 + (lane & 7) + 8 * ((lane >> 4) & 1);
                int kdc  = 2 * ks + ((lane >> 3) & 1);
                unsigned off = krow * 128 + (((kdc ^ (krow & 7))) << 4);
                LDSM4(bh[q4], st + off);
                LDSM4(bl[q4], st + 4096 + off);
            }
            #pragma unroll
            for (int mt = 0; mt < 2; ++mt) {
                MMA4F(s[mt][0], qh_f[mt][ks], bh[0][0], bh[0][1]);
                MMA4F(s[mt][1], qh_f[mt][ks], bh[0][2], bh[0][3]);
                MMA4F(s[mt][2], qh_f[mt][ks], bh[1][0], bh[1][1]);
                MMA4F(s[mt][3], qh_f[mt][ks], bh[1][2], bh[1][3]);
                MMA4F(s[mt][0], qh_f[mt][ks], bl[0][0], bl[0][1]);
                MMA4F(s[mt][1], qh_f[mt][ks], bl[0][2], bl[0][3]);
                MMA4F(s[mt][2], qh_f[mt][ks], bl[1][0], bl[1][1]);
                MMA4F(s[mt][3], qh_f[mt][ks], bl[1][2], bl[1][3]);
            }
        }

        // ---- online softmax (base-2 domain), per m-tile ----
        #pragma unroll
        for (int mt = 0; mt < 2; ++mt)
            #pragma unroll
            for (int r = 0; r < 2; ++r) {
                float mx = -1e30f;
                #pragma unroll
                for (int nt = 0; nt < 4; ++nt)
                    mx = fmaxf(mx, fmaxf(s[mt][nt][2*r], s[mt][nt][2*r+1]));
                mx = fmaxf(mx, __shfl_xor_sync(0xffffffffu, mx, 1));
                mx = fmaxf(mx, __shfl_xor_sync(0xffffffffu, mx, 2));
                float mnew  = fmaxf(s_m[mt][r], mx);
                float alpha = fexp2(s_m[mt][r] - mnew);
                float rs = 0.f;
                #pragma unroll
                for (int nt = 0; nt < 4; ++nt) {
                    float p0 = fexp2(s[mt][nt][2*r]   - mnew);
                    float p1 = fexp2(s[mt][nt][2*r+1] - mnew);
                    s[mt][nt][2*r] = p0; s[mt][nt][2*r+1] = p1;
                    rs += p0 + p1;
                }
                rs += __shfl_xor_sync(0xffffffffu, rs, 1);
                rs += __shfl_xor_sync(0xffffffffu, rs, 2);
                s_l[mt][r] = s_l[mt][r] * alpha + rs;
                s_m[mt][r] = mnew;
                #pragma unroll
                for (int nt = 0; nt < 8; ++nt) {
                    o[mt][nt][2*r] *= alpha; o[mt][nt][2*r+1] *= alpha;
                }
            }

        // ---- O += Ph Vh (V frags shared across m-tiles) ----
        #pragma unroll
        for (int ks = 0; ks < 2; ++ks) {
            unsigned pa[2][4];
            #pragma unroll
            for (int mt = 0; mt < 2; ++mt)
                #pragma unroll
                for (int e = 0; e < 4; ++e) {
                    int nt = 2 * ks + (e >> 1);
                    pa[mt][e] = pack_h2(s[mt][nt][(e & 1) * 2],
                                        s[mt][nt][(e & 1) * 2 + 1]);
                }
            #pragma unroll
            for (int dd = 0; dd < 4; dd += 2) {
                unsigned vh0[4], vh1[4];
                int vrow = 16 * ks + (lane & 15);
                {
                    int vdc = 2 * dd + (lane >> 4);
                    unsigned off = vrow * 128 + (((vdc ^ (vrow & 7))) << 4);
                    LDSM4T(vh0, st + 8192 + off);
                }
                {
                    int vdc = 2 * (dd + 1) + (lane >> 4);
                    unsigned off = vrow * 128 + (((vdc ^ (vrow & 7))) << 4);
                    LDSM4T(vh1, st + 8192 + off);
                }
                #pragma unroll
                for (int mt = 0; mt < 2; ++mt) {
                    MMA4F(o[mt][2*dd],   pa[mt], vh0[0], vh0[1]);
                    MMA4F(o[mt][2*dd+1], pa[mt], vh0[2], vh0[3]);
                    MMA4F(o[mt][2*dd+2], pa[mt], vh1[0], vh1[1]);
                    MMA4F(o[mt][2*dd+3], pa[mt], vh1[2], vh1[3]);
                }
            }
        }
    }

    // ---- epilogue: O/l, fp16 hi only at [b][s][h*64+d] ----
    #pragma unroll
    for (int mt = 0; mt < 2; ++mt) {
        float inv[2] = {1.f / s_l[mt][0], 1.f / s_l[mt][1]};
        #pragma unroll
        for (int nt = 0; nt < 8; ++nt) {
            int d = h * DK + nt * 8 + (lane & 3) * 2;
            #pragma unroll
            for (int r = 0; r < 2; ++r) {
                int srow = qt * 128 + 32 * w + mt * 16 + (lane >> 2) + 8 * r;
                size_t dst = (size_t)(b * SEQ + srow) * D_MODEL + d;
                *(unsigned*)(g_po + dst) =
                    pack_h2(o[mt][nt][2*r] * inv[r], o[mt][nt][2*r+1] * inv[r]);
            }
        }
    }
}

// ---------------- launcher --------------------------------------------------
extern "C" void kernel_launch(void* const* d_in, const int* in_sizes, int n_in,
                              void* d_out, int out_size) {
    const float* query = (const float*)d_in[0];
    const float* key   = (const float*)d_in[1];
    const float* value = (const float*)d_in[2];
    const float* Wq    = (const float*)d_in[3];
    const float* bq    = (const float*)d_in[4];
    const float* Wk    = (const float*)d_in[5];
    const float* bk    = (const float*)d_in[6];
    const float* Wv    = (const float*)d_in[7];
    const float* bv    = (const float*)d_in[8];
    const float* Wo    = (const float*)d_in[9];
    const float* bo    = (const float*)d_in[10];
    float* out = (float*)d_out;

    cudaFuncSetAttribute(tc_qkv,   cudaFuncAttributeMaxDynamicSharedMemorySize, G_SMEM);
    cudaFuncSetAttribute(tc_out,   cudaFuncAttributeMaxDynamicSharedMemorySize, G_SMEM);
    cudaFuncSetAttribute(attn_mma, cudaFuncAttributeMaxDynamicSharedMemorySize, A_SMEM);

    dim3 gS(592, 7);
    split_all<<<gS, 256>>>(query, key, value, Wq, Wk, Wv, Wo);

    dim3 gQKV(D_MODEL / 128, MTOT / 128, 3);   // (8, 32, 3)
    tc_qkv<<<gQKV, 128, G_SMEM>>>(bq, bk, bv);

    dim3 gAtt(SEQ / 128, NHEAD, BATCH);        // (16, 16, 2)
    attn_mma<<<gAtt, 128, A_SMEM>>>();

    dim3 gOut(D_MODEL / 128, MTOT / 128, 1);   // (8, 32)
    tc_out<<<gOut, 128, G_SMEM>>>(bo, out);
}